// round 11
// baseline (speedup 1.0000x reference)
#include <cuda_runtime.h>
#include <cuda_bf16.h>
#include <cstdint>
#include <cstddef>

#define BB 128
#define TT 2048
#define II 64
#define HH 128
#define GG 512                 // 4*H
#define BT (BB * TT)

// ---- recurrence config: 256 threads, 2 rows/thread, shfl-paired gates ------
#define REGK 104               // W_hh cols per row held in registers
#define SMEMK (HH - REGK)      // 24 cols in SMEM
#define NSQ (SMEMK / 4)        // 6 ulonglong2 groups per row

typedef unsigned long long u64;

// 512MB scratch for x_proj[row][g], row = b*T + t, g in [0,512)
__device__ float g_xproj[(size_t)BT * GG];

__device__ __forceinline__ u64 pk(float lo, float hi) {
    u64 r; asm("mov.b64 %0,{%1,%2};" : "=l"(r) : "f"(lo), "f"(hi)); return r;
}
__device__ __forceinline__ void upk(u64 v, float& lo, float& hi) {
    asm("mov.b64 {%0,%1},%2;" : "=f"(lo), "=f"(hi) : "l"(v));
}
// packed fp32x2 FMA (sm_103a): d.lo += a.lo*b.lo ; d.hi += a.hi*b.hi
__device__ __forceinline__ void fma2(u64& d, u64 a, u64 b) {
    asm("fma.rn.f32x2 %0,%1,%2,%0;" : "+l"(d) : "l"(a), "l"(b));
}

__device__ __forceinline__ float sigmoidf_(float x) {
    return 1.0f / (1.0f + __expf(-x));
}
__device__ __forceinline__ float tanhf_(float x) {
    float xc = fminf(fmaxf(x, -15.0f), 15.0f);
    float e = __expf(-2.0f * xc);
    return (1.0f - e) / (1.0f + e);
}

// ---------------------------------------------------------------------------
// Phase 1: g_xproj[row][512] = W_ih @ x[row] + (b_ih + b_hh)   (unchanged)
// ---------------------------------------------------------------------------
__global__ __launch_bounds__(512, 1) void xproj_kernel(
    const float* __restrict__ x, const float* __restrict__ Wih,
    const float* __restrict__ bih, const float* __restrict__ bhh)
{
    extern __shared__ float sm1[];
    float* wsg  = sm1;                   // [64][512] k-major
    float* bsum = wsg + 64 * 512;        // [512]
    float* xs   = bsum + 512;            // [64 k][68 rows] padded

    const int tid = threadIdx.x;

    for (int idx = tid; idx < 64 * 512; idx += 512) {
        int k = idx >> 9, c = idx & 511;
        wsg[idx] = Wih[c * 64 + k];
    }
    bsum[tid] = bih[tid] + bhh[tid];
    __syncthreads();

    const int lane = tid & 31, wrp = tid >> 5;
    const int r0 = (wrp & 7) * 8;
    const int cb = (wrp >> 3) * 256 + lane * 4;

    u64 bp[4];
    {
        float4 t0 = *(const float4*)&bsum[cb];
        float4 t1 = *(const float4*)&bsum[cb + 128];
        bp[0] = pk(t0.x, t0.y); bp[1] = pk(t0.z, t0.w);
        bp[2] = pk(t1.x, t1.y); bp[3] = pk(t1.z, t1.w);
    }

    for (int tile = blockIdx.x; tile < BT / 64; tile += gridDim.x) {
        __syncthreads();
        for (int idx = tid; idx < 64 * 64; idx += 512) {
            int r = idx >> 6, k = idx & 63;
            xs[k * 68 + r] = x[(size_t)tile * 64 * 64 + idx];
        }
        __syncthreads();

        u64 acc[8][4];
        #pragma unroll
        for (int ri = 0; ri < 8; ri++) {
            acc[ri][0] = bp[0]; acc[ri][1] = bp[1];
            acc[ri][2] = bp[2]; acc[ri][3] = bp[3];
        }

        #pragma unroll 8
        for (int k = 0; k < 64; k++) {
            float4 w0 = *(const float4*)&wsg[k * 512 + cb];
            float4 w1 = *(const float4*)&wsg[k * 512 + cb + 128];
            u64 wa = pk(w0.x, w0.y), wb = pk(w0.z, w0.w);
            u64 wc = pk(w1.x, w1.y), wd = pk(w1.z, w1.w);
            float4 xa = *(const float4*)&xs[k * 68 + r0];
            float4 xb = *(const float4*)&xs[k * 68 + r0 + 4];
            float xv[8] = {xa.x, xa.y, xa.z, xa.w, xb.x, xb.y, xb.z, xb.w};
            #pragma unroll
            for (int ri = 0; ri < 8; ri++) {
                u64 xx = pk(xv[ri], xv[ri]);
                fma2(acc[ri][0], wa, xx); fma2(acc[ri][1], wb, xx);
                fma2(acc[ri][2], wc, xx); fma2(acc[ri][3], wd, xx);
            }
        }

        #pragma unroll
        for (int ri = 0; ri < 8; ri++) {
            size_t row = (size_t)tile * 64 + r0 + ri;
            float a0,a1,a2,a3,a4,a5,a6,a7;
            upk(acc[ri][0], a0, a1); upk(acc[ri][1], a2, a3);
            upk(acc[ri][2], a4, a5); upk(acc[ri][3], a6, a7);
            *(float4*)&g_xproj[row * GG + cb]       = make_float4(a0,a1,a2,a3);
            *(float4*)&g_xproj[row * GG + cb + 128] = make_float4(a4,a5,a6,a7);
        }
    }
}

// ---------------------------------------------------------------------------
// Phase 2: LSTM recurrence. One CTA per batch (128 CTAs, one wave).
// 256 threads; SHUFFLE PAIRING: warp w lane l -> unit jh = w*16 + (l&15),
// bit = (l>>4)&1. bit=0 owns rows (i=jh, g=jh+256); bit=1 owns
// (f=jh+128, o=jh+384). Activations exchanged via shfl.bfly 16 (same warp)
// -> NO gact SMEM round-trip, ONE barrier per step (double-buffered h).
// W_hh[row][0:104] in regs (2 x 52 u64); [104:128) in SMEM ulonglong2.
// SMEM: ws2 6*512*16 = 49152, h 2*128*4 = 1024 -> 50176B
// ---------------------------------------------------------------------------
__global__ __launch_bounds__(256, 1) void lstm_kernel(
    const float* __restrict__ Whh, const float* __restrict__ h0,
    const float* __restrict__ c0, float* __restrict__ out)
{
    extern __shared__ char sm2c[];
    ulonglong2* ws2 = (ulonglong2*)sm2c;                 // [NSQ][512]
    float*      h_s = (float*)(sm2c + NSQ * 512 * 16);   // [2][128]

    const int tid = threadIdx.x;          // 0..255
    const int l   = tid & 31, w = tid >> 5;
    const int bit = (l >> 4) & 1;         // partner selector within warp
    const int jh  = w * 16 + (l & 15);    // hidden unit index
    const int b   = blockIdx.x;
    const int rA  = jh + 128 * bit;       // i (bit=0) or f (bit=1)
    const int rB  = jh + 256 + 128 * bit; // g (bit=0) or o (bit=1)

    // --- register weights: rows rA, rB cols [0,104) as 52 u64 each ---
    u64 wA[REGK / 2], wB[REGK / 2];
    {
        const float* a  = Whh + rA * HH;
        const float* bq = Whh + rB * HH;
        #pragma unroll
        for (int q = 0; q < REGK / 4; q++) {
            float4 v = *(const float4*)&a[4 * q];
            wA[2 * q] = pk(v.x, v.y); wA[2 * q + 1] = pk(v.z, v.w);
            float4 wv = *(const float4*)&bq[4 * q];
            wB[2 * q] = pk(wv.x, wv.y); wB[2 * q + 1] = pk(wv.z, wv.w);
        }
    }
    // --- SMEM weights: ws2[q*512 + r] = cols [104+4q .. 104+4q+3] of row r ---
    for (int idx = tid; idx < NSQ * 512; idx += 256) {
        int q = idx >> 9, r = idx & 511;
        float4 v = *(const float4*)&Whh[r * HH + REGK + 4 * q];
        ulonglong2 u; u.x = pk(v.x, v.y); u.y = pk(v.z, v.w);
        ws2[idx] = u;
    }
    // --- initial state (both partner threads carry c redundantly) ---
    float c = c0[b * HH + jh];
    if (tid < HH) h_s[tid] = h0[b * HH + tid];
    __syncthreads();

    const float* xp = g_xproj + (size_t)b * TT * GG;
    float* enc = out + BB * HH + (size_t)b * TT * HH;

    int p = 0;
    float xgA = xp[rA];                    // prefetch t = 0
    float xgB = xp[rB];
    for (int t = 0; t < TT; t++) {
        float xa = xgA, xb = xgB;
        if (t + 1 < TT) {                  // prefetch next step
            xgA = xp[(size_t)(t + 1) * GG + rA];
            xgB = xp[(size_t)(t + 1) * GG + rB];
        }

        const ulonglong2* hb2 = (const ulonglong2*)&h_s[p * HH];  // 32 pairs
        u64 aA0 = 0ULL, aA1 = 0ULL, aB0 = 0ULL, aB1 = 0ULL;

        // register part: k in [0, 104) -> 26 LDS.128 broadcasts
        #pragma unroll
        for (int q = 0; q < REGK / 4; q++) {
            ulonglong2 hh = hb2[q];
            fma2(aA0, wA[2 * q],     hh.x); fma2(aB0, wB[2 * q],     hh.x);
            fma2(aA1, wA[2 * q + 1], hh.y); fma2(aB1, wB[2 * q + 1], hh.y);
        }
        // SMEM part: k in [104, 128) -> 6 broadcasts + 12 weight LDS.128
        #pragma unroll
        for (int q = 0; q < NSQ; q++) {
            ulonglong2 hh = hb2[REGK / 4 + q];
            ulonglong2 wa = ws2[q * 512 + rA];
            ulonglong2 wb = ws2[q * 512 + rB];
            fma2(aA0, wa.x, hh.x); fma2(aA1, wa.y, hh.y);
            fma2(aB0, wb.x, hh.x); fma2(aB1, wb.y, hh.y);
        }

        float s0, s1, s2, s3;
        upk(aA0, s0, s1); upk(aA1, s2, s3);
        float gA = xa + (s0 + s1) + (s2 + s3);
        upk(aB0, s0, s1); upk(aB1, s2, s3);
        float gB = xb + (s0 + s1) + (s2 + s3);

        // activations: bit=0 -> (i, g), bit=1 -> (f, o)
        float act0 = sigmoidf_(gA);
        float act1 = bit ? sigmoidf_(gB) : tanhf_(gB);
        // exchange with partner lane (l ^ 16) — same warp, no barrier
        float oth0 = __shfl_xor_sync(0xffffffffu, act0, 16);
        float oth1 = __shfl_xor_sync(0xffffffffu, act1, 16);
        float ig = bit ? oth0 : act0;
        float gg = bit ? oth1 : act1;
        float fg = bit ? act0 : oth0;
        float og = bit ? act1 : oth1;

        c = fg * c + ig * gg;
        if (!bit) {                        // only bit=0 produces h
            float hn = og * tanhf_(c);
            h_s[(p ^ 1) * HH + jh] = hn;
            enc[(size_t)t * HH + jh] = hn;
        }
        __syncthreads();                   // single barrier per step
        p ^= 1;
    }

    if (!bit) out[b * HH + jh] = h_s[p * HH + jh];   // h_last
}

extern "C" void kernel_launch(void* const* d_in, const int* in_sizes, int n_in,
                              void* d_out, int out_size) {
    const float* x    = (const float*)d_in[0];   // [B,T,I]
    const float* h0   = (const float*)d_in[1];   // [B,H]
    const float* c0   = (const float*)d_in[2];   // [B,H]
    const float* Wih  = (const float*)d_in[3];   // [4H,I]
    const float* Whh  = (const float*)d_in[4];   // [4H,H]
    const float* bih  = (const float*)d_in[5];   // [4H]
    const float* bhh  = (const float*)d_in[6];   // [4H]
    float* out = (float*)d_out;                  // [B*H] h_last, then [B,T,H]

    constexpr int SMEM1 = (64 * 512 + 512 + 64 * 68) * 4;   // 150528
    constexpr int SMEM2 = NSQ * 512 * 16 + 2 * HH * 4;      // 50176

    cudaFuncSetAttribute(xproj_kernel,
        cudaFuncAttributeMaxDynamicSharedMemorySize, SMEM1);
    cudaFuncSetAttribute(lstm_kernel,
        cudaFuncAttributeMaxDynamicSharedMemorySize, SMEM2);

    xproj_kernel<<<148, 512, SMEM1>>>(x, Wih, bih, bhh);
    lstm_kernel<<<BB, 256, SMEM2>>>(Whh, h0, c0, out);
}

// round 12
// speedup vs baseline: 1.2725x; 1.2725x over previous
#include <cuda_runtime.h>
#include <cuda_bf16.h>
#include <cstdint>
#include <cstddef>

#define BB 128
#define TT 2048
#define II 64
#define HH 128
#define GG 512                 // 4*H
#define BT (BB * TT)

// ---- recurrence config: 256 threads, 2 rows/thread --------------------------
#define REGK 104               // W_hh cols per row held in registers
#define SMEMK (HH - REGK)      // 24 cols in SMEM
#define NSQ (SMEMK / 4)        // 6 ulonglong2 groups per row

typedef unsigned long long u64;

// 512MB scratch for x_proj[row][g], row = b*T + t, g in [0,512)
__device__ float g_xproj[(size_t)BT * GG];

__device__ __forceinline__ u64 pk(float lo, float hi) {
    u64 r; asm("mov.b64 %0,{%1,%2};" : "=l"(r) : "f"(lo), "f"(hi)); return r;
}
__device__ __forceinline__ void upk(u64 v, float& lo, float& hi) {
    asm("mov.b64 {%0,%1},%2;" : "=f"(lo), "=f"(hi) : "l"(v));
}
// packed fp32x2 FMA (sm_103a): d.lo += a.lo*b.lo ; d.hi += a.hi*b.hi
__device__ __forceinline__ void fma2(u64& d, u64 a, u64 b) {
    asm("fma.rn.f32x2 %0,%1,%2,%0;" : "+l"(d) : "l"(a), "l"(b));
}

// HW tanh (sm_75+): single ~16-cyc op, rel err ~2^-10.8
__device__ __forceinline__ float tanh_ap(float x) {
    float y; asm("tanh.approx.f32 %0, %1;" : "=f"(y) : "f"(x)); return y;
}
__device__ __forceinline__ float sigmoid_ap(float x) {
    return fmaf(0.5f, tanh_ap(0.5f * x), 0.5f);
}

// ---------------------------------------------------------------------------
// Phase 1: g_xproj[row][512] = W_ih @ x[row] + (b_ih + b_hh)   (unchanged)
// ---------------------------------------------------------------------------
__global__ __launch_bounds__(512, 1) void xproj_kernel(
    const float* __restrict__ x, const float* __restrict__ Wih,
    const float* __restrict__ bih, const float* __restrict__ bhh)
{
    extern __shared__ float sm1[];
    float* wsg  = sm1;                   // [64][512] k-major
    float* bsum = wsg + 64 * 512;        // [512]
    float* xs   = bsum + 512;            // [64 k][68 rows] padded

    const int tid = threadIdx.x;

    for (int idx = tid; idx < 64 * 512; idx += 512) {
        int k = idx >> 9, c = idx & 511;
        wsg[idx] = Wih[c * 64 + k];
    }
    bsum[tid] = bih[tid] + bhh[tid];
    __syncthreads();

    const int lane = tid & 31, wrp = tid >> 5;
    const int r0 = (wrp & 7) * 8;
    const int cb = (wrp >> 3) * 256 + lane * 4;

    u64 bp[4];
    {
        float4 t0 = *(const float4*)&bsum[cb];
        float4 t1 = *(const float4*)&bsum[cb + 128];
        bp[0] = pk(t0.x, t0.y); bp[1] = pk(t0.z, t0.w);
        bp[2] = pk(t1.x, t1.y); bp[3] = pk(t1.z, t1.w);
    }

    for (int tile = blockIdx.x; tile < BT / 64; tile += gridDim.x) {
        __syncthreads();
        for (int idx = tid; idx < 64 * 64; idx += 512) {
            int r = idx >> 6, k = idx & 63;
            xs[k * 68 + r] = x[(size_t)tile * 64 * 64 + idx];
        }
        __syncthreads();

        u64 acc[8][4];
        #pragma unroll
        for (int ri = 0; ri < 8; ri++) {
            acc[ri][0] = bp[0]; acc[ri][1] = bp[1];
            acc[ri][2] = bp[2]; acc[ri][3] = bp[3];
        }

        #pragma unroll 8
        for (int k = 0; k < 64; k++) {
            float4 w0 = *(const float4*)&wsg[k * 512 + cb];
            float4 w1 = *(const float4*)&wsg[k * 512 + cb + 128];
            u64 wa = pk(w0.x, w0.y), wb = pk(w0.z, w0.w);
            u64 wc = pk(w1.x, w1.y), wd = pk(w1.z, w1.w);
            float4 xa = *(const float4*)&xs[k * 68 + r0];
            float4 xb = *(const float4*)&xs[k * 68 + r0 + 4];
            float xv[8] = {xa.x, xa.y, xa.z, xa.w, xb.x, xb.y, xb.z, xb.w};
            #pragma unroll
            for (int ri = 0; ri < 8; ri++) {
                u64 xx = pk(xv[ri], xv[ri]);
                fma2(acc[ri][0], wa, xx); fma2(acc[ri][1], wb, xx);
                fma2(acc[ri][2], wc, xx); fma2(acc[ri][3], wd, xx);
            }
        }

        #pragma unroll
        for (int ri = 0; ri < 8; ri++) {
            size_t row = (size_t)tile * 64 + r0 + ri;
            float a0,a1,a2,a3,a4,a5,a6,a7;
            upk(acc[ri][0], a0, a1); upk(acc[ri][1], a2, a3);
            upk(acc[ri][2], a4, a5); upk(acc[ri][3], a6, a7);
            *(float4*)&g_xproj[row * GG + cb]       = make_float4(a0,a1,a2,a3);
            *(float4*)&g_xproj[row * GG + cb + 128] = make_float4(a4,a5,a6,a7);
        }
    }
}

// ---------------------------------------------------------------------------
// Phase 2: LSTM recurrence (R10 structure — measured best — + HW tanh).
// One CTA per batch (128 CTAs, one wave). 256 threads; thread tid owns gate
// rows tid and tid+256; threads tid and tid+128 together hold all 4 gates of
// hidden unit jh = tid & 127.
// W_hh[row][0:104] in registers (2 x 52 u64); [104:128) in SMEM as
// ulonglong2 [6][512] -> 12 LDS.128/thread. h broadcast as LDS.128 pairs.
// Activations packed as float2: gAB[jh]={i,g}, gAB[128+jh]={f,o}.
// SMEM: ws2 6*512*16 = 49152, h 2*128*4 = 1024, gAB 256*8 = 2048 -> 52224B
// ---------------------------------------------------------------------------
__global__ __launch_bounds__(256, 1) void lstm_kernel(
    const float* __restrict__ Whh, const float* __restrict__ h0,
    const float* __restrict__ c0, float* __restrict__ out)
{
    extern __shared__ char sm2c[];
    ulonglong2* ws2 = (ulonglong2*)sm2c;                 // [NSQ][512]
    float*      h_s = (float*)(sm2c + NSQ * 512 * 16);   // [2][128]
    float2*     gAB = (float2*)(h_s + 2 * HH);           // [256]

    const int tid = threadIdx.x;          // 0..255
    const int jh  = tid & 127;            // hidden unit index
    const int b   = blockIdx.x;
    const int rA  = tid;                  // row A: i (tid<128) or f
    const int rB  = tid + 256;            // row B: g (tid<128) or o

    // --- register weights: rows rA, rB cols [0,104) as 52 u64 each ---
    u64 wA[REGK / 2], wB[REGK / 2];
    {
        const float* a  = Whh + rA * HH;
        const float* bq = Whh + rB * HH;
        #pragma unroll
        for (int q = 0; q < REGK / 4; q++) {
            float4 v = *(const float4*)&a[4 * q];
            wA[2 * q] = pk(v.x, v.y); wA[2 * q + 1] = pk(v.z, v.w);
            float4 w = *(const float4*)&bq[4 * q];
            wB[2 * q] = pk(w.x, w.y); wB[2 * q + 1] = pk(w.z, w.w);
        }
    }
    // --- SMEM weights: ws2[q*512 + r] = cols [104+4q, 104+4q+3] of row r ---
    for (int idx = tid; idx < NSQ * 512; idx += 256) {
        int q = idx >> 9, r = idx & 511;
        float4 v = *(const float4*)&Whh[r * HH + REGK + 4 * q];
        ulonglong2 u; u.x = pk(v.x, v.y); u.y = pk(v.z, v.w);
        ws2[idx] = u;
    }
    // --- initial state (both partner threads carry c redundantly) ---
    float c = c0[b * HH + jh];
    if (tid < HH) h_s[tid] = h0[b * HH + tid];
    __syncthreads();

    const float* xp = g_xproj + (size_t)b * TT * GG;
    float* enc = out + BB * HH + (size_t)b * TT * HH;

    int p = 0;
    float xgA = xp[rA];                    // prefetch t = 0
    float xgB = xp[rB];
    for (int t = 0; t < TT; t++) {
        float xa = xgA, xb = xgB;
        if (t + 1 < TT) {                  // prefetch next step
            xgA = xp[(size_t)(t + 1) * GG + rA];
            xgB = xp[(size_t)(t + 1) * GG + rB];
        }

        const ulonglong2* hb2 = (const ulonglong2*)&h_s[p * HH];  // 32 pairs
        u64 aA0 = 0ULL, aA1 = 0ULL, aB0 = 0ULL, aB1 = 0ULL;

        // register part: k in [0, 104) -> 26 LDS.128 broadcasts
        #pragma unroll
        for (int q = 0; q < REGK / 4; q++) {
            ulonglong2 hh = hb2[q];
            fma2(aA0, wA[2 * q],     hh.x); fma2(aB0, wB[2 * q],     hh.x);
            fma2(aA1, wA[2 * q + 1], hh.y); fma2(aB1, wB[2 * q + 1], hh.y);
        }
        // SMEM part: k in [104, 128) -> 6 broadcasts + 12 weight LDS.128
        #pragma unroll
        for (int q = 0; q < NSQ; q++) {
            ulonglong2 hh = hb2[REGK / 4 + q];
            ulonglong2 wa = ws2[q * 512 + rA];
            ulonglong2 wb = ws2[q * 512 + rB];
            fma2(aA0, wa.x, hh.x); fma2(aA1, wa.y, hh.y);
            fma2(aB0, wb.x, hh.x); fma2(aB1, wb.y, hh.y);
        }

        float s0, s1, s2, s3;
        upk(aA0, s0, s1); upk(aA1, s2, s3);
        float gA = xa + (s0 + s1) + (s2 + s3);
        upk(aB0, s0, s1); upk(aB1, s2, s3);
        float gB = xb + (s0 + s1) + (s2 + s3);

        // distributed activations (HW tanh), packed for the phase-B gather:
        // tid<128: rows (i, g) -> gAB[jh] = {sig(gA), tanh(gB)}
        // tid>=128: rows (f, o) -> gAB[128+jh] = {sig(gA), sig(gB)}
        float act0 = sigmoid_ap(gA);
        float act1 = (tid < 128) ? tanh_ap(gB) : sigmoid_ap(gB);
        gAB[tid] = make_float2(act0, act1);
        __syncthreads();

        // phase B (redundant across the partner pair; c stays consistent)
        float2 vig = gAB[jh];          // {i, g}
        float2 vfo = gAB[128 + jh];    // {f, o}
        c = vfo.x * c + vig.x * vig.y;
        if (tid < 128) {
            float hn = vfo.y * tanh_ap(c);
            h_s[(p ^ 1) * HH + jh] = hn;
            enc[(size_t)t * HH + jh] = hn;
        }
        __syncthreads();
        p ^= 1;
    }

    if (tid < HH) out[b * HH + tid] = h_s[p * HH + tid];   // h_last
}

extern "C" void kernel_launch(void* const* d_in, const int* in_sizes, int n_in,
                              void* d_out, int out_size) {
    const float* x    = (const float*)d_in[0];   // [B,T,I]
    const float* h0   = (const float*)d_in[1];   // [B,H]
    const float* c0   = (const float*)d_in[2];   // [B,H]
    const float* Wih  = (const float*)d_in[3];   // [4H,I]
    const float* Whh  = (const float*)d_in[4];   // [4H,H]
    const float* bih  = (const float*)d_in[5];   // [4H]
    const float* bhh  = (const float*)d_in[6];   // [4H]
    float* out = (float*)d_out;                  // [B*H] h_last, then [B,T,H]

    constexpr int SMEM1 = (64 * 512 + 512 + 64 * 68) * 4;          // 150528
    constexpr int SMEM2 = NSQ * 512 * 16 + 2 * HH * 4 + 256 * 8;   // 52224

    cudaFuncSetAttribute(xproj_kernel,
        cudaFuncAttributeMaxDynamicSharedMemorySize, SMEM1);
    cudaFuncSetAttribute(lstm_kernel,
        cudaFuncAttributeMaxDynamicSharedMemorySize, SMEM2);

    xproj_kernel<<<148, 512, SMEM1>>>(x, Wih, bih, bhh);
    lstm_kernel<<<BB, 256, SMEM2>>>(Whh, h0, c0, out);
}